// round 17
// baseline (speedup 1.0000x reference)
#include <cuda_runtime.h>
#include <math.h>
#include <stdint.h>

// ---------------- static problem config ----------------
#define BB 32
#define TT 12
#define NNODE 500
#define NSKIPC 256
#define NENDC 512
#define NPREDC 12
#define LL 8
#define RFh 13
#define BN_EPS 1e-5f

typedef unsigned long long ull;
typedef unsigned int u32;

__device__ __forceinline__ float to_tf32(float x) {
    u32 r; asm("cvt.rna.tf32.f32 %0, %1;" : "=r"(r) : "f"(x));
    return __uint_as_float(r);
}
__device__ __forceinline__ void mma_tf32(float* c, const u32* a, const u32* b) {
    asm("mma.sync.aligned.m16n8k8.row.col.f32.tf32.tf32.f32 "
        "{%0,%1,%2,%3},{%4,%5,%6,%7},{%8,%9},{%0,%1,%2,%3};"
        : "+f"(c[0]), "+f"(c[1]), "+f"(c[2]), "+f"(c[3])
        : "r"(a[0]), "r"(a[1]), "r"(a[2]), "r"(a[3]), "r"(b[0]), "r"(b[1]));
}
__device__ __forceinline__ void cp16(float* dst, const float* src, int bytes) {
    u32 d = (u32)__cvta_generic_to_shared(dst);
    asm volatile("cp.async.cg.shared.global [%0], [%1], 16, %2;\n"
                 :: "r"(d), "l"(src), "r"(bytes));
}

// ---------------- device scratch ----------------
__device__ float g_P[NNODE * 64];
__device__ float g_Q[NNODE * 64];
__device__ float g_eraw[2 * NNODE * NNODE];
__device__ float g_Scat[NNODE * 2000];            // tf32-rounded supports [A0|A0^2|A1|A1^2]
__device__ float g_tmp[BB * TT * 32 * 2];
__device__ float g_X0[BB * 32 * RFh * NNODE];     // tf32-rounded
__device__ float g_X1[BB * 32 * RFh * NNODE];     // tf32-rounded
__device__ float g_D[BB * 32 * 12 * NNODE];       // direct gc-part (x-block @ XG), rows (b*32+o)*To+t
__device__ float g_Z[12288 * 2000];               // Zcat (tf32), rows (b*32+o)*To+t, cols e*500+v
__device__ float g_XGcat[BB * 256 * NNODE];       // tf32-rounded last-t gated slices
__device__ float g_Wcat[256 * 256];               // tf32-rounded
__device__ float g_skip[BB * NSKIPC * NNODE];
__device__ float g_Srelu[BB * NNODE * NSKIPC];    // tf32-rounded
__device__ float g_o1wT[NSKIPC * NENDC];          // tf32-rounded
__device__ float g_stats2[7 * 64];                // per-layer BN stats accumulators (atomic)
__device__ float g_Wz[7 * 160 * 32];              // tf32 Z-weights [layer][r][c]; r<128: e=r>>5,o=r&31 diff; r>=128: direct

// ---------------- fused one-time prep ----------------
__global__ void k_prep(const float* __restrict__ skp_w, const float* __restrict__ o1w,
                       const float* __restrict__ gcw) {
    int idx = blockIdx.x * 256 + threadIdx.x;
    if (idx < 7 * 64) g_stats2[idx] = 0.f;
    if (idx < 65536) {
        int o = idx >> 8, r = idx & 255, l = r >> 5, c = r & 31;
        g_Wcat[idx] = to_tf32(skp_w[l * 8192 + o * 32 + c]);
    }
    if (idx < 131072) {
        int h = idx / NSKIPC, c = idx % NSKIPC;
        g_o1wT[c * NENDC + h] = to_tf32(o1w[idx]);
    }
    if (idx < 7 * 160 * 32) {
        int l = idx / 5120, rem = idx % 5120, r = rem >> 5, c = rem & 31;
        float w;
        if (r < 128) { int e = r >> 5, o = r & 31; w = gcw[l * 5120 + o * 160 + 32 + e * 32 + c]; }
        else         { int o = r - 128;            w = gcw[l * 5120 + o * 160 + c]; }
        g_Wz[idx] = to_tf32(w);
    }
}

__device__ __forceinline__ int wfrow(int o) {   // o: 0-31 filter ch, 32-63 gate ch
    int oo = o & 31;
    return ((oo >> 3) << 4) + (oo & 7) + ((o < 32) ? 0 : 8);
}

// ---------------- adjacency ----------------
__global__ void k_pq(const float* __restrict__ factor, const float* __restrict__ map_w,
                     const float* __restrict__ map_b,
                     const float* __restrict__ a1w, const float* __restrict__ a1b) {
    __shared__ float vv[32];
    int j = blockIdx.x, h = threadIdx.x;
    if (h < 32) {
        float acc = map_b[h];
#pragma unroll
        for (int u = 0; u < 32; u++) acc += factor[j * 32 + u] * map_w[u * 32 + h];
        vv[h] = fmaxf(acc, 0.f);
    }
    __syncthreads();
    float p = 0.f, q = a1b[h];
#pragma unroll
    for (int d = 0; d < 32; d++) {
        p += vv[d] * a1w[d * 64 + h];
        q += vv[d] * a1w[(32 + d) * 64 + h];
    }
    g_P[j * 64 + h] = p;
    g_Q[j * 64 + h] = q;
}

__global__ void k_adjmlp(const float* __restrict__ a2w, const float* __restrict__ a2b,
                         const float* __restrict__ a3w, const float* __restrict__ a3b) {
    __shared__ float Pt[128][65];
    __shared__ __align__(16) float sA2[64][32];
    __shared__ float sQ[64];
    __shared__ float sA3[64];
    __shared__ float sA2b[32];
    __shared__ float sA3b[2];
    int i = blockIdx.x, tid = threadIdx.x;
    for (int k = tid; k < 64 * 32; k += 128) sA2[k / 32][k % 32] = a2w[k];
    if (tid < 64) { sQ[tid] = g_Q[i * 64 + tid]; sA3[tid] = a3w[tid]; }
    if (tid < 32) sA2b[tid] = a2b[tid];
    if (tid < 2) sA3b[tid] = a3b[tid];
    for (int j0 = 0; j0 < NNODE; j0 += 128) {
        __syncthreads();
        int cnt = min(128, NNODE - j0);
        for (int k = tid; k < cnt * 64; k += 128)
            Pt[k / 64][k % 64] = g_P[(j0 + (k / 64)) * 64 + (k % 64)];
        __syncthreads();
        if (tid < cnt) {
            int j = j0 + tid;
            float h1[64];
#pragma unroll
            for (int h = 0; h < 64; h++) h1[h] = fmaxf(Pt[tid][h] + sQ[h], 0.f);
            float e0 = sA3b[0], e1 = sA3b[1];
#pragma unroll
            for (int c = 0; c < 32; c++) {
                float acc = sA2b[c];
#pragma unroll
                for (int h = 0; h < 64; h++) acc += h1[h] * sA2[h][c];
                acc = fmaxf(acc, 0.f);
                e0 += acc * sA3[c * 2];
                e1 += acc * sA3[c * 2 + 1];
            }
            g_eraw[i * NNODE + j] = e0;
            g_eraw[NNODE * NNODE + i * NNODE + j] = e1;
        }
    }
}

__global__ void k_softmax(float* __restrict__ outSup, int writeSup) {
    int bid = blockIdx.x;
    int e = bid / NNODE, i = bid % NNODE;
    const float* row = g_eraw + e * NNODE * NNODE + i * NNODE;
    __shared__ float red[256];
    int tid = threadIdx.x;
    float m = -1e30f;
    for (int j = tid; j < NNODE; j += 256) m = fmaxf(m, row[j]);
    red[tid] = m; __syncthreads();
    for (int s = 128; s > 0; s >>= 1) { if (tid < s) red[tid] = fmaxf(red[tid], red[tid + s]); __syncthreads(); }
    m = red[0]; __syncthreads();
    float sum = 0.f;
    for (int j = tid; j < NNODE; j += 256) sum += expf(row[j] - m);
    red[tid] = sum; __syncthreads();
    for (int s = 128; s > 0; s >>= 1) { if (tid < s) red[tid] += red[tid + s]; __syncthreads(); }
    float inv = 1.f / red[0];
    for (int j = tid; j < NNODE; j += 256) {
        float p = expf(row[j] - m) * inv;
        if (j == i) p = fmaxf(p, 1.f);
        g_Scat[i * 2000 + e * 1000 + j] = to_tf32(p);
        if (writeSup) outSup[(e * NNODE + i) * NNODE + j] = p;
    }
}

// ---------------- tf32 tensor GEMM: cp.async 4-stage (A^2 / skip / head) ----------------
#define TG_SSZ 4736
#define TG_NST 4
#define TG_SMEM (TG_NST * TG_SSZ * 4)

__device__ __forceinline__ void tg_stage(float* As_s, float* Bs_s,
                                         const float* A, const float* B,
                                         int m0, int n0, int k0,
                                         int M, int N, int K, int lda, int ldb, int tid) {
#pragma unroll
    for (int i = 0; i < 2; i++) {
        int ch = tid + i * 256;
        int row = ch >> 2, kq = (ch & 3) * 4;
        int c = k0 + kq;
        int bytes = 0;
        if (m0 + row < M) {
            int rem = (K - c) * 4;
            bytes = rem > 16 ? 16 : (rem > 0 ? rem : 0);
        }
        cp16(As_s + row * 20 + kq, A + (size_t)(m0 + row) * lda + c, bytes);
    }
#pragma unroll
    for (int i = 0; i < 2; i++) {
        int ch = tid + i * 256;
        int kr = ch >> 5, nq = (ch & 31) * 4;
        int col = n0 + nq;
        int bytes = 0;
        if (k0 + kr < K) {
            int rem = (N - col) * 4;
            bytes = rem > 16 ? 16 : (rem > 0 ? rem : 0);
        }
        cp16(Bs_s + kr * 136 + nq, B + (size_t)(k0 + kr) * ldb + col, bytes);
    }
}

__global__ __launch_bounds__(256, 2)
void tgemm(const float* __restrict__ A, const float* __restrict__ B, float* __restrict__ C,
           int M, int N, int K, int lda, int ldb, int ldc,
           int sA, int sB, int sC, int roundC) {
    extern __shared__ float sdyn[];
    A += (size_t)blockIdx.z * sA;
    B += (size_t)blockIdx.z * sB;
    C += (size_t)blockIdx.z * sC;
    int tid = threadIdx.x;
    int m0 = blockIdx.y * 128, n0 = blockIdx.x * 128;
    int lane = tid & 31, wid = tid >> 5;
    int wm = wid & 1, wn = wid >> 1;
    int gid = lane >> 2, tig = lane & 3;

    float acc[4][4][4];
#pragma unroll
    for (int mi = 0; mi < 4; mi++)
#pragma unroll
        for (int ni = 0; ni < 4; ni++)
#pragma unroll
            for (int r = 0; r < 4; r++) acc[mi][ni][r] = 0.f;

    int nkt = (K + 15) / 16;
    int pre = nkt < 3 ? nkt : 3;
    for (int s = 0; s < pre; s++) {
        tg_stage(sdyn + s * TG_SSZ, sdyn + s * TG_SSZ + 2560, A, B,
                 m0, n0, s * 16, M, N, K, lda, ldb, tid);
        asm volatile("cp.async.commit_group;");
    }
    if (pre == 3)      asm volatile("cp.async.wait_group 2;");
    else if (pre == 2) asm volatile("cp.async.wait_group 1;");
    else               asm volatile("cp.async.wait_group 0;");
    __syncthreads();

    for (int kt = 0; kt < nkt; kt++) {
        if (kt + 3 < nkt) {
            int s = (kt + 3) & (TG_NST - 1);
            tg_stage(sdyn + s * TG_SSZ, sdyn + s * TG_SSZ + 2560, A, B,
                     m0, n0, (kt + 3) * 16, M, N, K, lda, ldb, tid);
            asm volatile("cp.async.commit_group;");
        }
        const float* As_s = sdyn + (kt & (TG_NST - 1)) * TG_SSZ;
        const float* Bs_s = As_s + 2560;
#pragma unroll
        for (int ks = 0; ks < 16; ks += 8) {
            u32 af[4][4];
            u32 bf[4][2];
#pragma unroll
            for (int mi = 0; mi < 4; mi++) {
                int mb = wm * 64 + mi * 16 + gid;
                af[mi][0] = __float_as_uint(As_s[mb * 20 + ks + tig]);
                af[mi][1] = __float_as_uint(As_s[(mb + 8) * 20 + ks + tig]);
                af[mi][2] = __float_as_uint(As_s[mb * 20 + ks + tig + 4]);
                af[mi][3] = __float_as_uint(As_s[(mb + 8) * 20 + ks + tig + 4]);
            }
#pragma unroll
            for (int ni = 0; ni < 4; ni++) {
                int nb = wn * 32 + ni * 8 + gid;
                bf[ni][0] = __float_as_uint(Bs_s[(ks + tig) * 136 + nb]);
                bf[ni][1] = __float_as_uint(Bs_s[(ks + tig + 4) * 136 + nb]);
            }
#pragma unroll
            for (int mi = 0; mi < 4; mi++)
#pragma unroll
                for (int ni = 0; ni < 4; ni++)
                    mma_tf32(acc[mi][ni], af[mi], bf[ni]);
        }
        if (kt + 1 < nkt) {
            int after = nkt - kt - 2;
            if (after >= 2)      asm volatile("cp.async.wait_group 2;");
            else if (after == 1) asm volatile("cp.async.wait_group 1;");
            else                 asm volatile("cp.async.wait_group 0;");
        }
        __syncthreads();
    }

#pragma unroll
    for (int mi = 0; mi < 4; mi++) {
        int r0 = m0 + wm * 64 + mi * 16 + gid;
        int r1 = r0 + 8;
#pragma unroll
        for (int ni = 0; ni < 4; ni++) {
            int cc = n0 + wn * 32 + ni * 8 + tig * 2;
            float c0 = acc[mi][ni][0], c1 = acc[mi][ni][1];
            float c2 = acc[mi][ni][2], c3 = acc[mi][ni][3];
            if (roundC) { c0 = to_tf32(c0); c1 = to_tf32(c1); c2 = to_tf32(c2); c3 = to_tf32(c3); }
            if (r0 < M) {
                if (cc + 1 < N) *(float2*)(C + (size_t)r0 * ldc + cc) = make_float2(c0, c1);
                else if (cc < N) C[(size_t)r0 * ldc + cc] = c0;
            }
            if (r1 < M) {
                if (cc + 1 < N) *(float2*)(C + (size_t)r1 * ldc + cc) = make_float2(c2, c3);
                else if (cc < N) C[(size_t)r1 * ldc + cc] = c2;
            }
        }
    }
}

// ---------------- biggemm: Xn = Zcat @ Astack + D + bias + BN-residual; stats ----------------
// K=2000 fixed; B rows k -> Scat[v=k%500][e=k/500 block]. N=500. M = gridDim.y*128.
__global__ __launch_bounds__(256, 2)
void biggemm(const float* __restrict__ Z, const float* __restrict__ Scat,
             const float* __restrict__ D, const float* __restrict__ Xc, float* __restrict__ Xn,
             const float* __restrict__ gcb,
             const float* __restrict__ statsPrev, float cntPrev,
             const float* __restrict__ bngP, const float* __restrict__ bnbP,
             float* __restrict__ statsOut,
             int M, int Tin, int Tout, int dd) {
    extern __shared__ float sdyn[];
    __shared__ float sbias[32], sA[32], sBsh[32], sSum[32], sSq[32];
    int tid = threadIdx.x;
    int m0 = blockIdx.y * 128, n0 = blockIdx.x * 128;
    int lane = tid & 31, wid = tid >> 5;
    int wm = wid & 1, wn = wid >> 1;
    int gid = lane >> 2, tig = lane & 3;

    // stage helper (A: Z rows; B: remapped Scat rows)
    auto stage = [&](float* As_s, float* Bs_s, int k0) {
#pragma unroll
        for (int i = 0; i < 2; i++) {
            int ch = tid + i * 256;
            int row = ch >> 2, kq = (ch & 3) * 4;
            int bytes = (m0 + row < M) ? 16 : 0;   // K=2000, no k tail
            cp16(As_s + row * 20 + kq, Z + (size_t)(m0 + row) * 2000 + k0 + kq, bytes);
        }
#pragma unroll
        for (int i = 0; i < 2; i++) {
            int ch = tid + i * 256;
            int kr = ch >> 5, nq = (ch & 31) * 4;
            int k = k0 + kr;
            int e = k / 500, v = k - e * 500;
            int col = n0 + nq;
            int rem = (NNODE - col) * 4;
            int bytes = rem > 16 ? 16 : (rem > 0 ? rem : 0);
            cp16(Bs_s + kr * 136 + nq, Scat + (size_t)v * 2000 + e * 500 + col, bytes);
        }
        asm volatile("cp.async.commit_group;");
    };

    if (tid < 32) {
        sbias[tid] = gcb[tid];
        float a = 1.f, sh = 0.f;
        if (statsPrev) {
            float mean = statsPrev[tid] / cntPrev;
            float var = statsPrev[32 + tid] / cntPrev - mean * mean;
            a = bngP[tid] * rsqrtf(var + BN_EPS);
            sh = bnbP[tid] - mean * a;
        }
        sA[tid] = a; sBsh[tid] = sh; sSum[tid] = 0.f; sSq[tid] = 0.f;
    }

    float acc[4][4][4];
#pragma unroll
    for (int mi = 0; mi < 4; mi++)
#pragma unroll
        for (int ni = 0; ni < 4; ni++)
#pragma unroll
            for (int r = 0; r < 4; r++) acc[mi][ni][r] = 0.f;

    const int nkt = 125;    // 2000 / 16
    for (int s = 0; s < 3; s++) stage(sdyn + s * TG_SSZ, sdyn + s * TG_SSZ + 2560, s * 16);
    asm volatile("cp.async.wait_group 2;");
    __syncthreads();

    for (int kt = 0; kt < nkt; kt++) {
        if (kt + 3 < nkt) {
            int s = (kt + 3) & (TG_NST - 1);
            stage(sdyn + s * TG_SSZ, sdyn + s * TG_SSZ + 2560, (kt + 3) * 16);
        }
        const float* As_s = sdyn + (kt & (TG_NST - 1)) * TG_SSZ;
        const float* Bs_s = As_s + 2560;
#pragma unroll
        for (int ks = 0; ks < 16; ks += 8) {
            u32 af[4][4];
            u32 bf[4][2];
#pragma unroll
            for (int mi = 0; mi < 4; mi++) {
                int mb = wm * 64 + mi * 16 + gid;
                af[mi][0] = __float_as_uint(As_s[mb * 20 + ks + tig]);
                af[mi][1] = __float_as_uint(As_s[(mb + 8) * 20 + ks + tig]);
                af[mi][2] = __float_as_uint(As_s[mb * 20 + ks + tig + 4]);
                af[mi][3] = __float_as_uint(As_s[(mb + 8) * 20 + ks + tig + 4]);
            }
#pragma unroll
            for (int ni = 0; ni < 4; ni++) {
                int nb = wn * 32 + ni * 8 + gid;
                bf[ni][0] = __float_as_uint(Bs_s[(ks + tig) * 136 + nb]);
                bf[ni][1] = __float_as_uint(Bs_s[(ks + tig + 4) * 136 + nb]);
            }
#pragma unroll
            for (int mi = 0; mi < 4; mi++)
#pragma unroll
                for (int ni = 0; ni < 4; ni++)
                    mma_tf32(acc[mi][ni], af[mi], bf[ni]);
        }
        if (kt + 1 < nkt) {
            int after = nkt - kt - 2;
            if (after >= 2)      asm volatile("cp.async.wait_group 2;");
            else if (after == 1) asm volatile("cp.async.wait_group 1;");
            else                 asm volatile("cp.async.wait_group 0;");
        }
        __syncthreads();
    }

    // epilogue: + D + bias + BN residual, write Xn (tf32), accumulate stats
    float lS[4] = {0.f, 0.f, 0.f, 0.f};     // per mi pair unused; do per-row accumulation
#pragma unroll
    for (int mi = 0; mi < 4; mi++) {
        int r0 = m0 + wm * 64 + mi * 16 + gid;
        int r1 = r0 + 8;
        int q0 = r0 / Tout, t0 = r0 - q0 * Tout, o0 = q0 & 31;
        int q1 = r1 / Tout, t1 = r1 - q1 * Tout, o1 = q1 & 31;
        float b0 = sbias[o0], a0 = sA[o0], s0 = sBsh[o0];
        float b1 = sbias[o1], a1 = sA[o1], s1 = sBsh[o1];
        size_t xc0 = ((size_t)q0 * Tin + t0 + dd) * NNODE;
        size_t xc1 = ((size_t)q1 * Tin + t1 + dd) * NNODE;
        float pS0 = 0.f, pQ0 = 0.f, pS1 = 0.f, pQ1 = 0.f;
#pragma unroll
        for (int ni = 0; ni < 4; ni++) {
            int cc = n0 + wn * 32 + ni * 8 + tig * 2;
            if (cc >= NNODE) continue;   // cc even, NNODE even -> pair safe
            float2 dv0 = *(const float2*)&D[(size_t)r0 * NNODE + cc];
            float2 rv0 = *(const float2*)&Xc[xc0 + cc];
            float v00 = to_tf32(acc[mi][ni][0] + dv0.x + b0 + rv0.x * a0 + s0);
            float v01 = to_tf32(acc[mi][ni][1] + dv0.y + b0 + rv0.y * a0 + s0);
            *(float2*)&Xn[(size_t)r0 * NNODE + cc] = make_float2(v00, v01);
            pS0 += v00 + v01; pQ0 += v00 * v00 + v01 * v01;
            float2 dv1 = *(const float2*)&D[(size_t)r1 * NNODE + cc];
            float2 rv1 = *(const float2*)&Xc[xc1 + cc];
            float v10 = to_tf32(acc[mi][ni][2] + dv1.x + b1 + rv1.x * a1 + s1);
            float v11 = to_tf32(acc[mi][ni][3] + dv1.y + b1 + rv1.y * a1 + s1);
            *(float2*)&Xn[(size_t)r1 * NNODE + cc] = make_float2(v10, v11);
            pS1 += v10 + v11; pQ1 += v10 * v10 + v11 * v11;
        }
#pragma unroll
        for (int off = 2; off; off >>= 1) {
            pS0 += __shfl_down_sync(0xffffffffu, pS0, off, 4);
            pQ0 += __shfl_down_sync(0xffffffffu, pQ0, off, 4);
            pS1 += __shfl_down_sync(0xffffffffu, pS1, off, 4);
            pQ1 += __shfl_down_sync(0xffffffffu, pQ1, off, 4);
        }
        if (tig == 0) {
            atomicAdd(&sSum[o0], pS0); atomicAdd(&sSq[o0], pQ0);
            atomicAdd(&sSum[o1], pS1); atomicAdd(&sSq[o1], pQ1);
        }
    }
    (void)lS;
    __syncthreads();
    if (tid < 64) {
        int o = tid & 31;
        atomicAdd(&statsOut[tid], (tid < 32) ? sSum[o] : sSq[o]);
    }
}

// ---------------- gated conv GEMM + fused Z/D production ----------------
// X pre-rounded tf32. dyn smem: Bs[64][136] (reused as XGs[32][136]) + sWf[64][68]
#define GF_SMEM ((64 * 136 + 64 * 68) * 4)

__global__ __launch_bounds__(256)
void gfgemm(const float* __restrict__ X, float* __restrict__ XGcat,
            float* __restrict__ Zc, float* __restrict__ D,
            const float* __restrict__ fw, const float* __restrict__ fb,
            const float* __restrict__ gw, const float* __restrict__ gb,
            const float* __restrict__ Wz,
            const float* __restrict__ stats, float cnt,
            const float* __restrict__ bng, const float* __restrict__ bnb,
            int Tin, int Tout, int dd, int layer) {
    extern __shared__ float sm[];
    float* Bs = sm;                    // [64][136]; later XGs [32][136]
    float* sWf = sm + 64 * 136;        // [64][68]
    __shared__ float sab[64], sbf[64];
    int tid = threadIdx.x;
    int b = blockIdx.y;
    int n0 = blockIdx.x * 128;
    int ToutN = Tout * NNODE;
    int TinN = Tin * NNODE;
    const float* Xb = X + (size_t)b * 32 * TinN;

    int lane = tid & 31, wid = tid >> 5;
    int wm = wid & 3, wn = wid >> 2;
    int gid = lane >> 2, tig = lane & 3;

    // async B staging (raw bits)
    {
        int lr = tid >> 2, lq = tid & 3;
        size_t rbase = (size_t)(lr & 31) * TinN + (size_t)(lr >> 5) * (dd * NNODE);
        const float* src = Xb + rbase + n0;
#pragma unroll
        for (int i = 0; i < 8; i++) {
            int col = (lq + i * 4) * 4;
            int gcol = n0 + col;
            int rem = (ToutN - gcol) * 4;
            int bytes = rem > 16 ? 16 : (rem > 0 ? rem : 0);
            cp16(Bs + lr * 136 + col, src + col, bytes);
        }
        asm volatile("cp.async.commit_group;");
    }
    if (tid < 64) sbf[tid] = (tid < 32) ? fb[tid] : gb[tid & 31];
    if (tid < 32) {
        float a = 1.f, sh = 0.f;
        if (stats) {
            float mean = stats[tid] / cnt;
            float var = stats[32 + tid] / cnt - mean * mean;
            a = bng[tid] * rsqrtf(var + BN_EPS);
            sh = bnb[tid] - mean * a;
        }
        sab[tid] = a; sab[32 + tid] = sh;
    }
    __syncthreads();
    {
        int o = tid & 63, cg = tid >> 6;
        int oo = o & 31;
        const float* wsrc = (o < 32) ? fw : gw;
        int row = wfrow(o);
        float bsum = 0.f;
#pragma unroll
        for (int cc = 0; cc < 8; cc++) {
            int c = cg * 8 + cc;
            float a = sab[c], bb = sab[32 + c];
            float w0 = wsrc[oo * 64 + c * 2 + 0];
            float w1 = wsrc[oo * 64 + c * 2 + 1];
            sWf[row * 68 + c] = to_tf32(w0 * a);
            sWf[row * 68 + 32 + c] = to_tf32(w1 * a);
            bsum += (w0 + w1) * bb;
        }
        atomicAdd(&sbf[o], bsum);
    }
    asm volatile("cp.async.wait_group 0;");
    __syncthreads();

    u32 af[8][4];
    {
        int r0 = wm * 16 + gid, r1 = r0 + 8;
#pragma unroll
        for (int ks = 0; ks < 8; ks++) {
            af[ks][0] = __float_as_uint(sWf[r0 * 68 + ks * 8 + tig]);
            af[ks][1] = __float_as_uint(sWf[r1 * 68 + ks * 8 + tig]);
            af[ks][2] = __float_as_uint(sWf[r0 * 68 + ks * 8 + tig + 4]);
            af[ks][3] = __float_as_uint(sWf[r1 * 68 + ks * 8 + tig + 4]);
        }
    }

    float acc[8][4];
#pragma unroll
    for (int ni = 0; ni < 8; ni++)
#pragma unroll
        for (int r = 0; r < 4; r++) acc[ni][r] = 0.f;

#pragma unroll
    for (int ks = 0; ks < 8; ks++) {
#pragma unroll
        for (int ni = 0; ni < 8; ni++) {
            int nb = wn * 64 + ni * 8 + gid;
            u32 bfr[2] = { __float_as_uint(Bs[(ks * 8 + tig) * 136 + nb]),
                           __float_as_uint(Bs[(ks * 8 + tig + 4) * 136 + nb]) };
            mma_tf32(acc[ni], af[ks], bfr);
        }
    }
    __syncthreads();   // all warps done with Bs -> reuse as XGs

    // gated activation -> XGs (SMEM) + XGcat
    {
        int c = wm * 8 + gid;
        float bff = sbf[c], bfg = sbf[32 + c];
        size_t catbase = ((size_t)b * 256 + layer * 32 + c) * NNODE;
        int lastBase = (Tout - 1) * NNODE;
#pragma unroll
        for (int ni = 0; ni < 8; ni++) {
            int j = wn * 64 + ni * 8 + tig * 2;
            int gcol = n0 + j;
            if (gcol >= ToutN) continue;
            float f0 = acc[ni][0] + bff, f1 = acc[ni][1] + bff;
            float g0 = acc[ni][2] + bfg, g1 = acc[ni][3] + bfg;
            float v0 = to_tf32(tanhf(f0) * (1.f / (1.f + expf(-g0))));
            float v1 = to_tf32(tanhf(f1) * (1.f / (1.f + expf(-g1))));
            Bs[c * 136 + j] = v0;
            Bs[c * 136 + j + 1] = v1;
            if (gcol >= lastBase) {
                XGcat[catbase + (gcol - lastBase)] = v0;
                XGcat[catbase + (gcol - lastBase) + 1] = v1;
            }
        }
    }
    __syncthreads();
    if (!Wz) return;

    // Z GEMM: ZD[160][128] = Wz[160][32] @ XGs[32][128]
    {
        int hz = wid & 1;        // n-half (64 cols)
        int mg = wid >> 1;       // 0..3
#pragma unroll
        for (int mi = 0; mi < 3; mi++) {
            int mt = mg + mi * 4;
            if (mt >= 10) break;
            int r0 = mt * 16 + gid, r1 = r0 + 8;
            u32 azf[4][4];
#pragma unroll
            for (int s = 0; s < 4; s++) {
                azf[s][0] = __float_as_uint(Wz[r0 * 32 + s * 8 + tig]);
                azf[s][1] = __float_as_uint(Wz[r1 * 32 + s * 8 + tig]);
                azf[s][2] = __float_as_uint(Wz[r0 * 32 + s * 8 + tig + 4]);
                azf[s][3] = __float_as_uint(Wz[r1 * 32 + s * 8 + tig + 4]);
            }
#pragma unroll
            for (int ni = 0; ni < 8; ni++) {
                int nb = hz * 64 + ni * 8 + gid;
                float az[4] = {0.f, 0.f, 0.f, 0.f};
#pragma unroll
                for (int s = 0; s < 4; s++) {
                    u32 bfr[2] = { __float_as_uint(Bs[(s * 8 + tig) * 136 + nb]),
                                   __float_as_uint(Bs[(s * 8 + tig + 4) * 136 + nb]) };
                    mma_tf32(az, azf[s], bfr);
                }
                int cc = hz * 64 + ni * 8 + tig * 2;
                int gcol = n0 + cc;
                if (gcol >= ToutN) continue;
                int t = gcol / NNODE, n = gcol - t * NNODE;   // pairs never cross t (n even)
                // row r0
                {
                    int r = r0;
                    if (r < 128) {
                        int e = r >> 5, o = r & 31;
                        size_t zr = ((size_t)(b * 32 + o) * Tout + t) * 2000 + e * 500 + n;
                        *(float2*)&Zc[zr] = make_float2(to_tf32(az[0]), to_tf32(az[1]));
                    } else {
                        int o = r - 128;
                        size_t dr = ((size_t)(b * 32 + o) * Tout + t) * NNODE + n;
                        *(float2*)&D[dr] = make_float2(az[0], az[1]);
                    }
                }
                // row r1
                {
                    int r = r1;
                    if (r < 128) {
                        int e = r >> 5, o = r & 31;
                        size_t zr = ((size_t)(b * 32 + o) * Tout + t) * 2000 + e * 500 + n;
                        *(float2*)&Zc[zr] = make_float2(to_tf32(az[2]), to_tf32(az[3]));
                    } else {
                        int o = r - 128;
                        size_t dr = ((size_t)(b * 32 + o) * Tout + t) * NNODE + n;
                        *(float2*)&D[dr] = make_float2(az[2], az[3]);
                    }
                }
            }
        }
    }
}

// ---------------- input split + enter ----------------
__global__ void k_tmp(const float* __restrict__ inputs, const float* __restrict__ factor) {
    int t = blockIdx.x, b = blockIdx.y, tid = threadIdx.x;
    int o = tid >> 2, r = tid & 3;
    int u = o >> 1, f = o & 1;
    const float* inp = inputs + ((size_t)(b * TT + t) * NNODE) * 2 + f;
    float acc = 0.f;
    for (int n = r; n < NNODE; n += 4) acc += inp[n * 2] * factor[n * 32 + u];
    acc += __shfl_down_sync(0xffffffffu, acc, 2);
    acc += __shfl_down_sync(0xffffffffu, acc, 1);
    if (r == 0) g_tmp[(b * TT + t) * 64 + o] = acc;
}

__global__ void k_enter(const float* __restrict__ inputs, const float* __restrict__ factor,
                        const float* __restrict__ ew, const float* __restrict__ eb,
                        float* __restrict__ X0) {
    __shared__ float sw[128], sb[32], stmp[64];
    int b = blockIdx.z, tp = blockIdx.y;
    int tid = threadIdx.x;
    if (tid < 128) sw[tid] = ew[tid];
    if (tid < 32) sb[tid] = eb[tid];
    if (tp > 0 && tid < 64) stmp[tid] = g_tmp[(b * TT + (tp - 1)) * 64 + tid];
    __syncthreads();
    int n = blockIdx.x * 128 + tid;
    if (n >= NNODE) return;
    if (tp == 0) {
#pragma unroll
        for (int o = 0; o < 32; o++)
            X0[((size_t)(b * 32 + o) * RFh + 0) * NNODE + n] = to_tf32(sb[o]);
    } else {
        int t = tp - 1;
        float s0 = 0.f, s1 = 0.f;
#pragma unroll
        for (int u = 0; u < 32; u++) {
            float fv = factor[n * 32 + u];
            s0 += fv * stmp[u * 2];
            s1 += fv * stmp[u * 2 + 1];
        }
        float i0 = inputs[((size_t)(b * TT + t) * NNODE + n) * 2 + 0];
        float i1 = inputs[((size_t)(b * TT + t) * NNODE + n) * 2 + 1];
        float r0 = i0 - s0, r1 = i1 - s1;
#pragma unroll
        for (int o = 0; o < 32; o++) {
            float v = sb[o] + sw[o * 4] * s0 + sw[o * 4 + 1] * s1 + sw[o * 4 + 2] * r0 + sw[o * 4 + 3] * r1;
            X0[((size_t)(b * 32 + o) * RFh + tp) * NNODE + n] = to_tf32(v);
        }
    }
}

// ---------------- output head ----------------
__global__ void k_transpose_skip(const float* __restrict__ skip, const float* __restrict__ skp_b,
                                 float* __restrict__ Srelu) {
    __shared__ float tile[32][33];
    int b = blockIdx.z;
    int n0 = blockIdx.x * 32, c0 = blockIdx.y * 32;
    int n = n0 + threadIdx.x, c = c0 + threadIdx.y;
    tile[threadIdx.y][threadIdx.x] = (n < NNODE) ? skip[(size_t)(b * NSKIPC + c) * NNODE + n] : 0.f;
    __syncthreads();
    int n2 = n0 + threadIdx.y, c2 = c0 + threadIdx.x;
    float bsum = 0.f;
#pragma unroll
    for (int l = 0; l < LL; l++) bsum += skp_b[l * 256 + c2];
    if (n2 < NNODE)
        Srelu[(size_t)(b * NNODE + n2) * NSKIPC + c2] =
            to_tf32(fmaxf(tile[threadIdx.x][threadIdx.y] + bsum, 0.f));
}

__global__ void k_headfinal(const float* __restrict__ H, const float* __restrict__ o1b,
                            const float* __restrict__ o2w, const float* __restrict__ o2b,
                            float* __restrict__ out) {
    int warp = threadIdx.x >> 5, lane = threadIdx.x & 31;
    int row = blockIdx.x * 4 + warp;
    if (row >= BB * NNODE) return;
    int b = row / NNODE, n = row % NNODE;
    const float* Hr = H + (size_t)row * NENDC;
    float h[16];
#pragma unroll
    for (int i = 0; i < 16; i++)
        h[i] = fmaxf(Hr[lane + i * 32] + o1b[lane + i * 32], 0.f);
#pragma unroll
    for (int p = 0; p < NPREDC; p++) {
        float acc = 0.f;
#pragma unroll
        for (int i = 0; i < 16; i++) acc += o2w[p * NENDC + lane + i * 32] * h[i];
#pragma unroll
        for (int off = 16; off; off >>= 1) acc += __shfl_down_sync(0xffffffffu, acc, off);
        if (lane == 0) out[(size_t)(b * NPREDC + p) * NNODE + n] = acc + o2b[p];
    }
}

// ---------------- host launcher ----------------
extern "C" void kernel_launch(void* const* d_in, const int* in_sizes, int n_in,
                              void* d_out, int out_size) {
    const float* inputs = (const float*)d_in[0];
    const float* factor = (const float*)d_in[1];
    const float* map_w  = (const float*)d_in[2];
    const float* map_b  = (const float*)d_in[3];
    const float* a1w    = (const float*)d_in[4];
    const float* a1b    = (const float*)d_in[5];
    const float* a2w    = (const float*)d_in[6];
    const float* a2b    = (const float*)d_in[7];
    const float* a3w    = (const float*)d_in[8];
    const float* a3b    = (const float*)d_in[9];
    const float* enter_w = (const float*)d_in[10];
    const float* enter_b = (const float*)d_in[11];
    const float* filt_w = (const float*)d_in[12];
    const float* filt_b = (const float*)d_in[13];
    const float* gate_w = (const float*)d_in[14];
    const float* gate_b = (const float*)d_in[15];
    const float* skp_w  = (const float*)d_in[16];
    const float* skp_b  = (const float*)d_in[17];
    const float* gc_w   = (const float*)d_in[18];
    const float* gc_b   = (const float*)d_in[19];
    const float* bn_g   = (const float*)d_in[20];
    const float* bn_b   = (const float*)d_in[21];
    const float* o1w    = (const float*)d_in[22];
    const float* o1b    = (const float*)d_in[23];
    const float* o2w    = (const float*)d_in[24];
    const float* o2b    = (const float*)d_in[25];

    cudaFuncSetAttribute(tgemm, cudaFuncAttributeMaxDynamicSharedMemorySize, TG_SMEM);
    cudaFuncSetAttribute(biggemm, cudaFuncAttributeMaxDynamicSharedMemorySize, TG_SMEM);
    cudaFuncSetAttribute(gfgemm, cudaFuncAttributeMaxDynamicSharedMemorySize, GF_SMEM);

    float *pScat, *pZ, *pD, *pX0, *pX1, *pXGcat, *pWcat, *pSkip, *pSrelu, *pO1T, *pStats, *pWz;
    cudaGetSymbolAddress((void**)&pScat, g_Scat);
    cudaGetSymbolAddress((void**)&pZ, g_Z);
    cudaGetSymbolAddress((void**)&pD, g_D);
    cudaGetSymbolAddress((void**)&pX0, g_X0);
    cudaGetSymbolAddress((void**)&pX1, g_X1);
    cudaGetSymbolAddress((void**)&pXGcat, g_XGcat);
    cudaGetSymbolAddress((void**)&pWcat, g_Wcat);
    cudaGetSymbolAddress((void**)&pSkip, g_skip);
    cudaGetSymbolAddress((void**)&pSrelu, g_Srelu);
    cudaGetSymbolAddress((void**)&pO1T, g_o1wT);
    cudaGetSymbolAddress((void**)&pStats, g_stats2);
    cudaGetSymbolAddress((void**)&pWz, g_Wz);

    float* out = (float*)d_out;
    const int ySize = BB * NPREDC * NNODE;
    const int supSize = 2 * NNODE * NNODE;
    int writeSup = (out_size >= ySize + supSize) ? 1 : 0;
    float* outSup = out + ySize;

    static const int Tin[LL] = {13, 12, 10, 9, 7, 6, 4, 3};
    static const int Dd[LL]  = {1, 2, 1, 2, 1, 2, 1, 2};
    static const int To[LL]  = {12, 10, 9, 7, 6, 4, 3, 1};

    k_tmp<<<dim3(TT, BB), 256>>>(inputs, factor);
    k_enter<<<dim3(4, RFh, BB), 128>>>(inputs, factor, enter_w, enter_b, pX0);
    k_prep<<<512, 256>>>(skp_w, o1w, gc_w);
    gfgemm<<<dim3((To[0] * NNODE + 127) / 128, BB), 256, GF_SMEM>>>(
        pX0, pXGcat, pZ, pD, filt_w, filt_b, gate_w, gate_b, pWz,
        nullptr, 1.f, bn_g, bn_b, Tin[0], To[0], Dd[0], 0);
    k_pq<<<NNODE, 64>>>(factor, map_w, map_b, a1w, a1b);
    k_adjmlp<<<NNODE, 128>>>(a2w, a2b, a3w, a3b);
    k_softmax<<<2 * NNODE, 256>>>(outSup, writeSup);
    tgemm<<<dim3(4, 4, 2), 256, TG_SMEM>>>(pScat, pScat, pScat + 500, 500, 500, 500,
                                           2000, 2000, 2000, 1000, 1000, 1000, 1);

    float* Xc = pX0;
    float* Xn = pX1;
    for (int i = 0; i < LL - 1; i++) {
        int M = BB * 32 * To[i];
        const float* stP = (i == 0) ? nullptr : (pStats + (i - 1) * 64);
        float cntP = (i == 0) ? 1.f : (float)(BB * To[i - 1] * NNODE);
        biggemm<<<dim3(4, M / 128), 256, TG_SMEM>>>(pZ, pScat, pD, Xc, Xn,
            gc_b + i * 32, stP, cntP,
            bn_g + ((i > 0) ? (i - 1) : 0) * 32, bn_b + ((i > 0) ? (i - 1) : 0) * 32,
            pStats + i * 64, M, Tin[i], To[i], Dd[i]);
        int j = i + 1;
        gfgemm<<<dim3((To[j] * NNODE + 127) / 128, BB), 256, GF_SMEM>>>(
            Xn, pXGcat, pZ, pD,
            filt_w + j * 2048, filt_b + j * 32, gate_w + j * 2048, gate_b + j * 32,
            (j < LL - 1) ? (pWz + j * 5120) : nullptr,
            pStats + i * 64, (float)(BB * To[i] * NNODE), bn_g + i * 32, bn_b + i * 32,
            Tin[j], To[j], Dd[j], j);
        float* t = Xc; Xc = Xn; Xn = t;
    }
    // skip = Wcat @ XGcat  (batched over b); reuse g_Z as head hidden H later
    tgemm<<<dim3(4, 2, BB), 256, TG_SMEM>>>(pWcat, pXGcat, pSkip, 256, NNODE, 256,
                                            256, NNODE, NNODE, 0, 256 * NNODE, 256 * NNODE, 0);
    k_transpose_skip<<<dim3(16, 8, BB), dim3(32, 32)>>>(pSkip, skp_b, pSrelu);
    tgemm<<<dim3(4, 125), 256, TG_SMEM>>>(pSrelu, pO1T, pZ, BB * NNODE, NENDC, NSKIPC,
                                          NSKIPC, NENDC, NENDC, 0, 0, 0, 0);
    k_headfinal<<<(BB * NNODE + 3) / 4, 128>>>(pZ, o1b, o2w, o2b, out);
}